// round 4
// baseline (speedup 1.0000x reference)
#include <cuda_runtime.h>
#include <cuda_bf16.h>
#include <math.h>

// Problem constants
#define BB 8
#define CC 64
#define HH 256
#define WW 256
#define HWN 65536              // H*W
#define NCH 32                 // pixel chunks per image for streaming kernels
#define CHPX 2048              // pixels per chunk (HWN / NCH)

// ---------------- scratch (device globals; no allocation allowed) ------------
__device__ float g_lk[BB * HWN];          // k logits
__device__ float g_t[BB * HWN];           // pre-conv spatial attention
__device__ float g_s[BB * HWN];           // sigmoid(conv(t))
__device__ float g_partmax[BB * NCH];
__device__ float g_gmax[BB];
__device__ float g_Zpart[BB * NCH];
__device__ float g_pooledpart[BB * NCH * CC];
__device__ float g_a[BB * CC];            // channel softmax
__device__ float g_weff[BB * CC];         // a^T Wq
__device__ float g_M1t[CC * CC];          // (Wout @ Wv_spa) transposed: [i][o]
__device__ float g_M2t[BB * CC * CC];     // (Wout diag(a) Wv_spe) transposed per batch

// ---------------- f32x2 packed math helpers (Blackwell) ----------------------
__device__ __forceinline__ unsigned long long pack2(float lo, float hi) {
    unsigned long long r;
    asm("mov.b64 %0, {%1,%2};" : "=l"(r) : "f"(lo), "f"(hi));
    return r;
}
__device__ __forceinline__ float2 unpack2(unsigned long long v) {
    float2 r;
    asm("mov.b64 {%0,%1}, %2;" : "=f"(r.x), "=f"(r.y) : "l"(v));
    return r;
}
__device__ __forceinline__ unsigned long long ffma2(unsigned long long a,
                                                    unsigned long long b,
                                                    unsigned long long c) {
    unsigned long long d;
    asm("fma.rn.f32x2 %0, %1, %2, %3;" : "=l"(d) : "l"(a), "l"(b), "l"(c));
    return d;
}

// ---------------- K1: k logits + per-chunk max -------------------------------
__global__ void k1_logits(const float* __restrict__ x, const float* __restrict__ Wk) {
    const int b = blockIdx.y;
    const int chunk = blockIdx.x;
    const int base = chunk * CHPX;
    const int tid = threadIdx.x;
    __shared__ float wk[CC];
    __shared__ float red[8];
    if (tid < CC) wk[tid] = Wk[tid];
    __syncthreads();

    float4 a0 = make_float4(0.f, 0.f, 0.f, 0.f);
    float4 a1 = make_float4(0.f, 0.f, 0.f, 0.f);
    #pragma unroll 8
    for (int c = 0; c < CC; ++c) {
        const float w = wk[c];
        const float4* xr = (const float4*)(x + ((size_t)b * CC + c) * HWN + base);
        float4 v0 = xr[tid];
        float4 v1 = xr[tid + 256];
        a0.x = fmaf(w, v0.x, a0.x); a0.y = fmaf(w, v0.y, a0.y);
        a0.z = fmaf(w, v0.z, a0.z); a0.w = fmaf(w, v0.w, a0.w);
        a1.x = fmaf(w, v1.x, a1.x); a1.y = fmaf(w, v1.y, a1.y);
        a1.z = fmaf(w, v1.z, a1.z); a1.w = fmaf(w, v1.w, a1.w);
    }
    float4* lk4 = (float4*)(g_lk + (size_t)b * HWN + base);
    lk4[tid] = a0;
    lk4[tid + 256] = a1;

    float m = fmaxf(fmaxf(fmaxf(a0.x, a0.y), fmaxf(a0.z, a0.w)),
                    fmaxf(fmaxf(a1.x, a1.y), fmaxf(a1.z, a1.w)));
    #pragma unroll
    for (int off = 16; off; off >>= 1)
        m = fmaxf(m, __shfl_xor_sync(0xffffffffu, m, off));
    if ((tid & 31) == 0) red[tid >> 5] = m;
    __syncthreads();
    if (tid == 0) {
        float mm = red[0];
        #pragma unroll
        for (int w = 1; w < 8; ++w) mm = fmaxf(mm, red[w]);
        g_partmax[b * NCH + chunk] = mm;
    }
}

// ---------------- K1b: reduce chunk maxima -----------------------------------
__global__ void k1b_max() {
    const int tid = threadIdx.x;
    if (tid < BB) {
        float m = -3.4e38f;
        for (int ch = 0; ch < NCH; ++ch) m = fmaxf(m, g_partmax[tid * NCH + ch]);
        g_gmax[tid] = m;
    }
}

// ---------------- K2: softmax-weighted pooling of x --------------------------
__global__ void k2_pool(const float* __restrict__ x) {
    const int b = blockIdx.y;
    const int chunk = blockIdx.x;
    const int base = chunk * CHPX;
    const int tid = threadIdx.x;
    __shared__ float es[CHPX];
    __shared__ float red[8];

    const float m = g_gmax[b];
    float zloc = 0.f;
    for (int i = tid; i < CHPX; i += 256) {
        float e = expf(g_lk[(size_t)b * HWN + base + i] - m);
        es[i] = e;
        zloc += e;
    }
    #pragma unroll
    for (int off = 16; off; off >>= 1)
        zloc += __shfl_xor_sync(0xffffffffu, zloc, off);
    if ((tid & 31) == 0) red[tid >> 5] = zloc;
    __syncthreads();
    if (tid == 0) {
        float z = 0.f;
        #pragma unroll
        for (int w = 0; w < 8; ++w) z += red[w];
        g_Zpart[b * NCH + chunk] = z;
    }
    __syncthreads();

    const float4* es4 = (const float4*)es;
    for (int c = 0; c < CC; ++c) {
        const float4* xr = (const float4*)(x + ((size_t)b * CC + c) * HWN + base);
        float loc = 0.f;
        #pragma unroll
        for (int j = 0; j < 2; ++j) {
            float4 v = xr[tid + j * 256];
            float4 e = es4[tid + j * 256];
            loc += v.x * e.x + v.y * e.y + v.z * e.z + v.w * e.w;
        }
        #pragma unroll
        for (int off = 16; off; off >>= 1)
            loc += __shfl_xor_sync(0xffffffffu, loc, off);
        if ((tid & 31) == 0) red[tid >> 5] = loc;
        __syncthreads();
        if (tid == 0) {
            float s = 0.f;
            #pragma unroll
            for (int w = 0; w < 8; ++w) s += red[w];
            g_pooledpart[((size_t)b * NCH + chunk) * CC + c] = s;
        }
        __syncthreads();
    }
}

// ---------------- K3: tiny channel-attention chain ---------------------------
// 512 threads, one block: thread = (b, c)
__global__ void k3_stats(const float* __restrict__ Wq, const float* __restrict__ Wup) {
    const int tid = threadIdx.x;
    const int b = tid >> 6;
    const int c = tid & 63;
    __shared__ float zs[BB];
    __shared__ float pooled[BB * CC];
    __shared__ float att[BB * CC];
    __shared__ float uu[BB * CC];
    __shared__ float as_[BB * CC];

    if (c == 0) {
        float z = 0.f;
        for (int ch = 0; ch < NCH; ++ch) z += g_Zpart[b * NCH + ch];
        zs[b] = z;
    }
    __syncthreads();
    {
        float s = 0.f;
        for (int ch = 0; ch < NCH; ++ch)
            s += g_pooledpart[((size_t)b * NCH + ch) * CC + c];
        pooled[tid] = s / zs[b];
    }
    __syncthreads();
    {
        float s = 0.f;
        #pragma unroll 8
        for (int i = 0; i < CC; ++i) s = fmaf(Wq[c * CC + i], pooled[b * CC + i], s);
        att[tid] = s;
    }
    __syncthreads();
    {
        float s = 0.f;
        #pragma unroll 8
        for (int i = 0; i < CC; ++i) s = fmaf(Wup[c * CC + i], att[b * CC + i], s);
        uu[tid] = s;
    }
    __syncthreads();
    {
        float m = -3.4e38f;
        for (int i = 0; i < CC; ++i) m = fmaxf(m, uu[b * CC + i]);
        float sum = 0.f;
        for (int i = 0; i < CC; ++i) sum += expf(uu[b * CC + i] - m);
        float a = expf(uu[tid] - m) / sum;
        as_[tid] = a;
        g_a[tid] = a;
    }
    __syncthreads();
    {
        float s = 0.f;
        #pragma unroll 8
        for (int o = 0; o < CC; ++o) s = fmaf(as_[b * CC + o], Wq[o * CC + c], s);
        g_weff[tid] = s;
    }
}

// ---------------- K3b: build M1^T and M2^T (transposed for K5) ---------------
__global__ void k3b_mats(const float* __restrict__ Wout,
                         const float* __restrict__ Wv_spe,
                         const float* __restrict__ Wv_spa) {
    const int blk = blockIdx.x;     // 0..7 -> M2[b], 8 -> M1
    const int tid = threadIdx.x;
    __shared__ float av[CC];
    if (blk < 8) {
        if (tid < CC) av[tid] = g_a[blk * CC + tid];
        __syncthreads();
    }
    for (int e = tid; e < CC * CC; e += 256) {
        const int o = e >> 6;
        const int i = e & 63;
        float sum = 0.f;
        if (blk < 8) {
            #pragma unroll 8
            for (int c = 0; c < CC; ++c)
                sum = fmaf(Wout[o * CC + c] * av[c], Wv_spe[c * CC + i], sum);
            g_M2t[(size_t)blk * CC * CC + i * CC + o] = sum;
        } else {
            #pragma unroll 8
            for (int c = 0; c < CC; ++c)
                sum = fmaf(Wout[o * CC + c], Wv_spa[c * CC + i], sum);
            g_M1t[i * CC + o] = sum;
        }
    }
}

// ---------------- K4: t = w_eff . x per pixel --------------------------------
__global__ void k4_dot(const float* __restrict__ x) {
    const int b = blockIdx.y;
    const int base = blockIdx.x * CHPX;
    const int tid = threadIdx.x;
    __shared__ float wk[CC];
    if (tid < CC) wk[tid] = g_weff[b * CC + tid];
    __syncthreads();

    float4 a0 = make_float4(0.f, 0.f, 0.f, 0.f);
    float4 a1 = make_float4(0.f, 0.f, 0.f, 0.f);
    #pragma unroll 8
    for (int c = 0; c < CC; ++c) {
        const float w = wk[c];
        const float4* xr = (const float4*)(x + ((size_t)b * CC + c) * HWN + base);
        float4 v0 = xr[tid];
        float4 v1 = xr[tid + 256];
        a0.x = fmaf(w, v0.x, a0.x); a0.y = fmaf(w, v0.y, a0.y);
        a0.z = fmaf(w, v0.z, a0.z); a0.w = fmaf(w, v0.w, a0.w);
        a1.x = fmaf(w, v1.x, a1.x); a1.y = fmaf(w, v1.y, a1.y);
        a1.z = fmaf(w, v1.z, a1.z); a1.w = fmaf(w, v1.w, a1.w);
    }
    float4* t4 = (float4*)(g_t + (size_t)b * HWN + base);
    t4[tid] = a0;
    t4[tid + 256] = a1;
}

// ---------------- K4b: 7x7 conv + sigmoid ------------------------------------
__global__ void k4b_conv(const float* __restrict__ Wnorm) {
    const int b = blockIdx.y;
    const int tid = threadIdx.x;
    const int p = blockIdx.x * 256 + tid;
    __shared__ float wn[49];
    if (tid < 49) wn[tid] = Wnorm[tid];
    __syncthreads();
    const int y = p >> 8;
    const int xx = p & 255;
    const float* tb = g_t + (size_t)b * HWN;
    float acc = 0.f;
    #pragma unroll
    for (int ky = 0; ky < 7; ++ky) {
        const int yy = y + ky - 3;
        const bool yok = (unsigned)yy < 256u;
        #pragma unroll
        for (int kx = 0; kx < 7; ++kx) {
            const int xc = xx + kx - 3;
            float v = (yok && (unsigned)xc < 256u) ? tb[yy * 256 + xc] : 0.f;
            acc = fmaf(wn[ky * 7 + kx], v, acc);
        }
    }
    g_s[(size_t)b * HWN + p] = 1.f / (1.f + expf(-acc));
}

// ---------------- K5: fused final GEMM-pair with f32x2 -----------------------
// out[b,o,n] = s[b,n]*M1@x + M2[b]@x. Block: 128 pixels, 256 threads.
// thread (rg,pg): outputs [4rg,4rg+4) x pixel-pairs [4pg,4pg+4).
__global__ void __launch_bounds__(256, 2)
k5_final(const float* __restrict__ x, float* __restrict__ out) {
    const int b = blockIdx.y;
    const int base = blockIdx.x * 128;
    const int tid = threadIdx.x;
    __shared__ float xs[CC * 128];
    __shared__ float ss[128];

    // load x tile [64 ch][128 px]
    const float* xb = x + (size_t)b * CC * HWN + base;
    float4* xs4 = (float4*)xs;
    for (int i = tid; i < CC * 32; i += 256) {
        const int c = i >> 5;
        const int k = i & 31;
        xs4[i] = ((const float4*)(xb + (size_t)c * HWN))[k];
    }
    if (tid < 128) ss[tid] = g_s[(size_t)b * HWN + base + tid];
    __syncthreads();

    const int rg = tid >> 4;   // output group 0..15
    const int pg = tid & 15;   // pixel-pair group 0..15

    unsigned long long acc1[4][4], acc2[4][4];
    #pragma unroll
    for (int i = 0; i < 4; ++i)
        #pragma unroll
        for (int j = 0; j < 4; ++j) { acc1[i][j] = 0ULL; acc2[i][j] = 0ULL; }

    const float4* w1g = (const float4*)g_M1t;                       // [c][o/4]
    const float4* w2g = (const float4*)(g_M2t + (size_t)b * CC * CC);

    #pragma unroll 4
    for (int c = 0; c < CC; ++c) {
        const float4 xa = xs4[c * 32 + 2 * pg];
        const float4 xv = xs4[c * 32 + 2 * pg + 1];
        unsigned long long xp0 = pack2(xa.x, xa.y);
        unsigned long long xp1 = pack2(xa.z, xa.w);
        unsigned long long xp2 = pack2(xv.x, xv.y);
        unsigned long long xp3 = pack2(xv.z, xv.w);
        const float4 w1 = w1g[c * 16 + rg];
        const float4 w2 = w2g[c * 16 + rg];
        const float wa1[4] = {w1.x, w1.y, w1.z, w1.w};
        const float wa2[4] = {w2.x, w2.y, w2.z, w2.w};
        #pragma unroll
        for (int i = 0; i < 4; ++i) {
            unsigned long long wd1 = pack2(wa1[i], wa1[i]);
            unsigned long long wd2 = pack2(wa2[i], wa2[i]);
            acc1[i][0] = ffma2(wd1, xp0, acc1[i][0]);
            acc1[i][1] = ffma2(wd1, xp1, acc1[i][1]);
            acc1[i][2] = ffma2(wd1, xp2, acc1[i][2]);
            acc1[i][3] = ffma2(wd1, xp3, acc1[i][3]);
            acc2[i][0] = ffma2(wd2, xp0, acc2[i][0]);
            acc2[i][1] = ffma2(wd2, xp1, acc2[i][1]);
            acc2[i][2] = ffma2(wd2, xp2, acc2[i][2]);
            acc2[i][3] = ffma2(wd2, xp3, acc2[i][3]);
        }
    }

    unsigned long long sp[4];
    #pragma unroll
    for (int j = 0; j < 4; ++j)
        sp[j] = pack2(ss[8 * pg + 2 * j], ss[8 * pg + 2 * j + 1]);

    #pragma unroll
    for (int i = 0; i < 4; ++i) {
        const int o = 4 * rg + i;
        float* op = out + ((size_t)b * CC + o) * HWN + base + 8 * pg;
        #pragma unroll
        for (int j = 0; j < 4; ++j) {
            unsigned long long r = ffma2(sp[j], acc1[i][j], acc2[i][j]);
            ((float2*)op)[j] = unpack2(r);
        }
    }
}

// ---------------- launch ------------------------------------------------------
extern "C" void kernel_launch(void* const* d_in, const int* in_sizes, int n_in,
                              void* d_out, int out_size) {
    const float* x      = (const float*)d_in[0];
    const float* Wq     = (const float*)d_in[1];
    const float* Wk     = (const float*)d_in[2];
    const float* Wv_spe = (const float*)d_in[3];
    const float* Wv_spa = (const float*)d_in[4];
    const float* Wup    = (const float*)d_in[5];
    const float* Wout   = (const float*)d_in[6];
    const float* Wnorm  = (const float*)d_in[7];
    float* out = (float*)d_out;

    k1_logits<<<dim3(NCH, BB), 256>>>(x, Wk);
    k1b_max<<<1, 32>>>();
    k2_pool<<<dim3(NCH, BB), 256>>>(x);
    k3_stats<<<1, 512>>>(Wq, Wup);
    k3b_mats<<<9, 256>>>(Wout, Wv_spe, Wv_spa);
    k4_dot<<<dim3(NCH, BB), 256>>>(x);
    k4b_conv<<<dim3(HWN / 256, BB), 256>>>(Wnorm);
    k5_final<<<dim3(HWN / 128, BB), 256>>>(x, out);
}